// round 4
// baseline (speedup 1.0000x reference)
#include <cuda_runtime.h>
#include <math.h>

#define B_  32
#define T_  1024
#define D_  256
#define U_  512
#define G3  1536          // 3*U
#define NCTA_SCAN 128

typedef unsigned long long ull;

// packed fp32x2 FMA: d = a*b + d (elementwise on the two fp32 halves)
#define FMA2(d_, a_, b_) \
    asm("fma.rn.f32x2 %0, %1, %2, %3;" : "=l"(d_) : "l"(a_), "l"(b_), "l"(d_))
// splat a scalar float into both halves of a 64-bit packed reg
#define SPLAT2(d_, s_) \
    asm("mov.b64 %0, {%1, %1};" : "=l"(d_) : "r"(__float_as_uint(s_)))

// ---------------- scratch (device globals: allocation-free contract) ----------
__device__ float g_xw[(size_t)T_ * B_ * G3];     // [T,B,3U] gate pre-activations
__device__ float g_out0[(size_t)T_ * B_ * U_];   // layer-0 outputs [T,B,U]
__device__ float g_pred0[(size_t)T_ * B_ * U_];  // layer-1 outputs
__device__ float g_pred1[(size_t)T_ * B_ * U_];  // layer-2 outputs
__device__ float g_h[2][B_ * U_];                // double-buffered hidden state
__device__ unsigned g_flags[NCTA_SCAN];          // per-CTA arrival flags

// ---------------- atomic-free grid barrier ------------------------------------
// Arrive: CTA stores flags[ctaid] = tval (release). Wait: threads 0..127 each
// acquire-poll one flag until >= tval. No atomic serialization.
__device__ __forceinline__ void flag_barrier(unsigned tval) {
    __syncthreads();                              // CTA's h-stores all issued
    if (threadIdx.x == 0) {
        __threadfence();                          // release: stores visible first
        asm volatile("st.relaxed.gpu.global.u32 [%0], %1;"
                     :: "l"(&g_flags[blockIdx.x]), "r"(tval) : "memory");
    }
    if (threadIdx.x < NCTA_SCAN) {
        unsigned v;
        do {
            asm volatile("ld.acquire.gpu.global.u32 %0, [%1];"
                         : "=r"(v) : "l"(&g_flags[threadIdx.x]) : "memory");
        } while (v < tval);
    }
    __syncthreads();                              // whole CTA ordered after all flags
}

// ---------------- init hidden state + zero barrier flags ----------------------
__global__ void init_h_kernel(float* __restrict__ h, const float* __restrict__ h0) {
    int i = blockIdx.x * blockDim.x + threadIdx.x;
    if (i < B_ * U_) h[i] = h0[i & (U_ - 1)];
    if (blockIdx.x == 0 && threadIdx.x < NCTA_SCAN) g_flags[threadIdx.x] = 0;
}

// ---------------- persistent GRU scan ----------------------------------------
// 128 CTAs x 256 threads. CTA owns units u0..u0+3 (12 gate-cols col-major in
// SMEM). Warp w -> batches 4w..4w+3. Lane l -> k in {4l+128*i2+0..3}.
__global__ void __launch_bounds__(256, 1) scan_kernel(
    const float* __restrict__ R,      // recurrent [U,3U]
    const float* __restrict__ brec,   // recurrent bias [3U]
    const float* __restrict__ xw,     // [T,B,3U]
    float* __restrict__ out,          // [T,B,U]
    float* __restrict__ hbuf0,        // h double buffer, parity 0
    float* __restrict__ hbuf1)        // h double buffer, parity 1
{
    __shared__ float ws[12 * U_];     // [c][k] col-major: 24 KB, conflict-free LDS.128

    const int tid = threadIdx.x;
    const int u0  = blockIdx.x * 4;

    for (int idx = tid; idx < U_ * 12; idx += 256) {
        int k = idx / 12, c = idx - k * 12;
        int g = c >> 2, j = c & 3;
        ws[c * U_ + k] = R[(size_t)k * G3 + g * U_ + u0 + j];
    }
    __syncthreads();

    const int w  = tid >> 5, l = tid & 31;
    const int b0 = w * 4;
    const int lb = l >> 2, uj = l & 3;
    const int gb = b0 + lb;
    const int gu = u0 + uj;
    const bool act = (l < 16);
    const unsigned bit0 = l & 1, bit1 = (l >> 1) & 1;
    const unsigned bit2 = (l >> 2) & 1, bit3 = (l >> 3) & 1;

    float bz = 0.f, brr = 0.f, bh = 0.f;
    if (act) {
        bz  = brec[gu];
        brr = brec[U_ + gu];
        bh  = brec[2 * U_ + gu];
    }

    // prefetch xw for t=0
    float xz = 0.f, xr = 0.f, xh = 0.f;
    if (act) {
        const float* xwt = xw + (size_t)gb * G3;
        xz = __ldg(xwt + gu);
        xr = __ldg(xwt + U_ + gu);
        xh = __ldg(xwt + 2 * U_ + gu);
    }

    for (int t = 0; t < T_; t++) {
        const float* hR = (t & 1) ? hbuf1 : hbuf0;
        float*       hW = (t & 1) ? hbuf0 : hbuf1;

        float hold = act ? __ldcg(hR + gb * U_ + gu) : 0.f;

        // ---- hoisted h loads: all 16 LDG.128 in flight (MLP=16) ----
        ulonglong2 hq[4][4];
        #pragma unroll
        for (int i2 = 0; i2 < 4; i2++)
            #pragma unroll
            for (int b = 0; b < 4; b++)
                hq[i2][b] = __ldcg((const ulonglong2*)(hR + (b0 + b) * U_ + 4 * l + 128 * i2));

        ull acc[4][12];
        #pragma unroll
        for (int b = 0; b < 4; b++)
            #pragma unroll
            for (int c = 0; c < 12; c++) acc[b][c] = 0ull;

        #pragma unroll
        for (int i2 = 0; i2 < 4; i2++) {
            const int ko = 4 * l + 128 * i2;
            #pragma unroll
            for (int c = 0; c < 12; c++) {
                ulonglong2 wq = *(const ulonglong2*)(ws + c * U_ + ko);
                #pragma unroll
                for (int b = 0; b < 4; b++) {
                    FMA2(acc[b][c], hq[i2][b].x, wq.x);
                    FMA2(acc[b][c], hq[i2][b].y, wq.y);
                }
            }
        }

        // ---- horizontal add of packed halves ----
        float A[4][12];
        #pragma unroll
        for (int b = 0; b < 4; b++)
            #pragma unroll
            for (int c = 0; c < 12; c++) {
                float2 v = *reinterpret_cast<float2*>(&acc[b][c]);
                A[b][c] = v.x + v.y;
            }

        // ---- compacted butterfly: live slots halve each stage ----
        // final owner: lane l -> b=bits[3:2], uj=bits[1:0], gates c = g*4+uj
        // s=16: full 48-slot exchange
        #pragma unroll
        for (int b = 0; b < 4; b++)
            #pragma unroll
            for (int c = 0; c < 12; c++)
                A[b][c] += __shfl_xor_sync(0xffffffffu, A[b][c], 16);
        // s=8: keep b where (b>>1)==bit3  -> 24 slots
        float B8[2][12];
        #pragma unroll
        for (int bl = 0; bl < 2; bl++)
            #pragma unroll
            for (int c = 0; c < 12; c++) {
                float keep = bit3 ? A[2 + bl][c] : A[bl][c];
                float send = bit3 ? A[bl][c]     : A[2 + bl][c];
                B8[bl][c] = keep + __shfl_xor_sync(0xffffffffu, send, 8);
            }
        // s=4: keep b-low == bit2 -> 12 slots
        float B4[12];
        #pragma unroll
        for (int c = 0; c < 12; c++) {
            float keep = bit2 ? B8[1][c] : B8[0][c];
            float send = bit2 ? B8[0][c] : B8[1][c];
            B4[c] = keep + __shfl_xor_sync(0xffffffffu, send, 4);
        }
        // s=2: keep uj-high == bit1 -> 6 slots
        float B2[3][2];
        #pragma unroll
        for (int g = 0; g < 3; g++)
            #pragma unroll
            for (int j = 0; j < 2; j++) {
                float keep = bit1 ? B4[g * 4 + 2 + j] : B4[g * 4 + j];
                float send = bit1 ? B4[g * 4 + j]     : B4[g * 4 + 2 + j];
                B2[g][j] = keep + __shfl_xor_sync(0xffffffffu, send, 2);
            }
        // s=1: keep uj-low == bit0 -> 3 slots (mz, mr, mh)
        float S[3];
        #pragma unroll
        for (int g = 0; g < 3; g++) {
            float keep = bit0 ? B2[g][1] : B2[g][0];
            float send = bit0 ? B2[g][0] : B2[g][1];
            S[g] = keep + __shfl_xor_sync(0xffffffffu, send, 1);
        }

        if (act) {
            float mz = S[0] + bz;
            float mr = S[1] + brr;
            float mh = S[2] + bh;
            float z  = 1.f / (1.f + expf(-(xz + mz)));
            float r  = 1.f / (1.f + expf(-(xr + mr)));
            float hh = tanhf(xh + r * mh);
            float hnew = z * hold + (1.f - z) * hh;
            out[((size_t)t * B_ + gb) * U_ + gu] = hnew;
            __stcg(hW + gb * U_ + gu, hnew + 0.1f * (hold - hnew));  // zoneout
        }

        // prefetch next step's xw BEFORE the barrier (hides DRAM latency)
        if (act && t + 1 < T_) {
            const float* xwt = xw + ((size_t)(t + 1) * B_ + gb) * G3;
            xz = __ldg(xwt + gu);
            xr = __ldg(xwt + U_ + gu);
            xh = __ldg(xwt + 2 * U_ + gu);
        }
        flag_barrier((unsigned)(t + 1));
    }
}

// ---------------- fp32 tiled GEMM with f32x2 (packed over n) ------------------
// C = rowmap(A0 + s1*A1 + s2*A2) @ W + bias
// permA/permC: row index = (m%32)*1024 + m/32 ([B,T,*] <-> [T,B,*])
__global__ void __launch_bounds__(256) gemm_kernel(
    const float* __restrict__ A0, const float* __restrict__ A1,
    const float* __restrict__ A2, const float* __restrict__ avec,
    int ia1, int ia2,
    const float* __restrict__ W, const float* __restrict__ bias,
    float* __restrict__ C, int M, int N, int K, int permA, int permC)
{
    __shared__ float As[16][64];
    __shared__ float Bs[16][64];
    const int tid = threadIdx.x;
    const int bm = blockIdx.x * 64;
    const int bn = blockIdx.y * 64;

    const int ar = tid >> 2,  ak = (tid & 3)  << 2;
    const int br = tid >> 4,  bc = (tid & 15) << 2;
    const int tm = (tid >> 4) << 2, tn = (tid & 15) << 2;

    const float s1 = A1 ? avec[ia1] : 0.f;
    const float s2 = A2 ? avec[ia2] : 0.f;

    const int m_a = bm + ar;
    const size_t arow = permA ? ((size_t)(m_a & 31) * T_ + (m_a >> 5)) : (size_t)m_a;
    const float* Ap0 = A0 + arow * K + ak;
    const float* Ap1 = A1 ? (A1 + arow * K + ak) : (const float*)0;
    const float* Ap2 = A2 ? (A2 + arow * K + ak) : (const float*)0;
    const float* Wp  = W + (size_t)br * N + bn + bc;

    ull acc2[4][2];
    #pragma unroll
    for (int i = 0; i < 4; i++) { acc2[i][0] = 0ull; acc2[i][1] = 0ull; }

    for (int k0 = 0; k0 < K; k0 += 16) {
        float4 av = *(const float4*)(Ap0 + k0);
        if (A1) {
            float4 t1 = *(const float4*)(Ap1 + k0);
            av.x += s1 * t1.x; av.y += s1 * t1.y; av.z += s1 * t1.z; av.w += s1 * t1.w;
        }
        if (A2) {
            float4 t2 = *(const float4*)(Ap2 + k0);
            av.x += s2 * t2.x; av.y += s2 * t2.y; av.z += s2 * t2.z; av.w += s2 * t2.w;
        }
        As[ak + 0][ar] = av.x; As[ak + 1][ar] = av.y;
        As[ak + 2][ar] = av.z; As[ak + 3][ar] = av.w;

        *(float4*)&Bs[br][bc] = *(const float4*)(Wp + (size_t)k0 * N);
        __syncthreads();

        #pragma unroll
        for (int kk = 0; kk < 16; kk++) {
            float4 a4 = *(const float4*)&As[kk][tm];
            ulonglong2 b2 = *(const ulonglong2*)&Bs[kk][tn];
            ull as0, as1, as2, as3;
            SPLAT2(as0, a4.x); SPLAT2(as1, a4.y);
            SPLAT2(as2, a4.z); SPLAT2(as3, a4.w);
            FMA2(acc2[0][0], as0, b2.x); FMA2(acc2[0][1], as0, b2.y);
            FMA2(acc2[1][0], as1, b2.x); FMA2(acc2[1][1], as1, b2.y);
            FMA2(acc2[2][0], as2, b2.x); FMA2(acc2[2][1], as2, b2.y);
            FMA2(acc2[3][0], as3, b2.x); FMA2(acc2[3][1], as3, b2.y);
        }
        __syncthreads();
    }

    #pragma unroll
    for (int i = 0; i < 4; i++) {
        int m = bm + tm + i;
        size_t crow = permC ? ((size_t)(m & 31) * T_ + (m >> 5)) : (size_t)m;
        float* cp = C + crow * N + bn + tn;
        #pragma unroll
        for (int jp = 0; jp < 2; jp++) {
            float2 v = *reinterpret_cast<float2*>(&acc2[i][jp]);
            cp[2 * jp + 0] = v.x + bias[bn + tn + 2 * jp + 0];
            cp[2 * jp + 1] = v.y + bias[bn + tn + 2 * jp + 1];
        }
    }
}

// ---------------- host orchestration -----------------------------------------
extern "C" void kernel_launch(void* const* d_in, const int* in_sizes, int n_in,
                              void* d_out, int out_size)
{
    const float* x   = (const float*)d_in[0];
    const float* k0  = (const float*)d_in[1];
    const float* r0  = (const float*)d_in[2];
    const float* b0  = (const float*)d_in[3];
    const float* ks  = (const float*)d_in[4];
    const float* rs  = (const float*)d_in[5];
    const float* bs  = (const float*)d_in[6];
    const float* h00 = (const float*)d_in[7];
    const float* h01 = (const float*)d_in[8];
    const float* h02 = (const float*)d_in[9];
    const float* a   = (const float*)d_in[10];
    const float* wd  = (const float*)d_in[11];
    const float* bd  = (const float*)d_in[12];

    float *xw, *out0, *p0, *p1, *hbase;
    cudaGetSymbolAddress((void**)&xw,    g_xw);
    cudaGetSymbolAddress((void**)&out0,  g_out0);
    cudaGetSymbolAddress((void**)&p0,    g_pred0);
    cudaGetSymbolAddress((void**)&p1,    g_pred1);
    cudaGetSymbolAddress((void**)&hbase, g_h);
    float* h0 = hbase;
    float* h1 = hbase + B_ * U_;

    const int M = B_ * T_;
    dim3 gridW(M / 64, G3 / 64);   // 512 x 24
    dim3 gridF(M / 64, D_ / 64);   // 512 x 4

    // ---- layer 0: xw = x @ k0 + b_in ----
    init_h_kernel<<<64, 256>>>(h0, h00);
    gemm_kernel<<<gridW, 256>>>(x, 0, 0, a, 0, 0, k0, b0, xw, M, G3, D_, 1, 0);
    scan_kernel<<<NCTA_SCAN, 256>>>(r0, b0 + G3, xw, out0, h0, h1);

    // ---- layer 1: input = out0 ----
    init_h_kernel<<<64, 256>>>(h0, h01);
    gemm_kernel<<<gridW, 256>>>(out0, 0, 0, a, 0, 0, ks, bs, xw, M, G3, U_, 0, 0);
    scan_kernel<<<NCTA_SCAN, 256>>>(rs, bs + G3, xw, p0, h0, h1);

    // ---- layer 2: input = out0 + a[0]*pred0 (fused into GEMM A-load) ----
    init_h_kernel<<<64, 256>>>(h0, h02);
    gemm_kernel<<<gridW, 256>>>(out0, p0, 0, a, 0, 0, ks, bs, xw, M, G3, U_, 0, 0);
    scan_kernel<<<NCTA_SCAN, 256>>>(rs, bs + G3, xw, p1, h0, h1);

    // ---- final: (out0 + a[1]*pred0 + a[2]*pred1) @ wd + bd -> [B,T,D] ----
    gemm_kernel<<<gridF, 256>>>(out0, p0, p1, a, 1, 2, wd, bd,
                                (float*)d_out, M, D_, U_, 0, 1);
}

// round 5
// speedup vs baseline: 1.0366x; 1.0366x over previous
#include <cuda_runtime.h>
#include <math.h>

#define B_  32
#define T_  1024
#define D_  256
#define U_  512
#define G3  1536          // 3*U
#define NCTA_SCAN 128

typedef unsigned long long ull;

// packed fp32x2 FMA: d = a*b + d (elementwise on the two fp32 halves)
#define FMA2(d_, a_, b_) \
    asm("fma.rn.f32x2 %0, %1, %2, %3;" : "=l"(d_) : "l"(a_), "l"(b_), "l"(d_))
// splat a scalar float into both halves of a 64-bit packed reg
#define SPLAT2(d_, s_) \
    asm("mov.b64 %0, {%1, %1};" : "=l"(d_) : "r"(__float_as_uint(s_)))

// ---------------- scratch (device globals: allocation-free contract) ----------
__device__ float g_xw[(size_t)T_ * B_ * G3];     // [T,B,3U] gate pre-activations
__device__ float g_out0[(size_t)T_ * B_ * U_];   // layer-0 outputs [T,B,U]
__device__ float g_pred0[(size_t)T_ * B_ * U_];  // layer-1 outputs
__device__ float g_pred1[(size_t)T_ * B_ * U_];  // layer-2 outputs
__device__ float g_h[2][B_ * U_];                // double-buffered hidden state
__device__ __align__(16) unsigned g_flags[NCTA_SCAN];  // per-CTA arrival flags

// ---------------- atomic-free grid barrier ------------------------------------
// Arrive: tid0 stores flags[cta] = tval (release). Wait: warp 0 polls all 128
// flags via 32 x v4 acquire loads. No atomic serialization anywhere.
__device__ __forceinline__ void flag_barrier(unsigned tval) {
    __syncthreads();                              // CTA's h-stores all issued
    if (threadIdx.x == 0) {
        __threadfence();                          // release
        asm volatile("st.relaxed.gpu.global.u32 [%0], %1;"
                     :: "l"(&g_flags[blockIdx.x]), "r"(tval) : "memory");
    }
    if (threadIdx.x < 32) {
        const unsigned* fp = &g_flags[threadIdx.x * 4];
        unsigned a, b, c, d;
        do {
            asm volatile("ld.acquire.gpu.global.v4.u32 {%0,%1,%2,%3}, [%4];"
                         : "=r"(a), "=r"(b), "=r"(c), "=r"(d) : "l"(fp) : "memory");
        } while (a < tval || b < tval || c < tval || d < tval);
    }
    __syncthreads();                              // CTA ordered after all flags
}

// ---------------- persistent GRU scan ----------------------------------------
// 128 CTAs x 256 threads. CTA owns units u0..u0+3 (12 gate-cols col-major in
// SMEM). Warp w -> batches 4w..4w+3. Lane l -> k in {4l+128*i2+0..3}.
// h-init is folded in (flags pre-zeroed by the preceding gemm launch).
__global__ void __launch_bounds__(256, 1) scan_kernel(
    const float* __restrict__ R,      // recurrent [U,3U]
    const float* __restrict__ brec,   // recurrent bias [3U]
    const float* __restrict__ h0vec,  // initial hidden [1,U]
    const float* __restrict__ xw,     // [T,B,3U]
    float* __restrict__ out,          // [T,B,U]
    float* __restrict__ hbuf0,        // h double buffer, parity 0
    float* __restrict__ hbuf1)        // h double buffer, parity 1
{
    __shared__ float ws[12 * U_];     // [c][k] col-major: 24 KB, conflict-free LDS.128

    const int tid = threadIdx.x;
    const int u0  = blockIdx.x * 4;

    // Preload the 12 recurrent columns this CTA owns.
    for (int idx = tid; idx < U_ * 12; idx += 256) {
        int k = idx / 12, c = idx - k * 12;
        int g = c >> 2, j = c & 3;
        ws[c * U_ + k] = R[(size_t)k * G3 + g * U_ + u0 + j];
    }

    // h init: this CTA writes its 128-element slice of hbuf0 (tiled h0).
    if (tid < 128) {
        int i = blockIdx.x * 128 + tid;
        hbuf0[i] = h0vec[i & (U_ - 1)];
    }

    const int w  = tid >> 5, l = tid & 31;
    const int b0 = w * 4;
    const int lb = l >> 2, uj = l & 3;
    const int gb = b0 + lb;
    const int gu = u0 + uj;
    const bool act = (l < 16);
    const unsigned bit0 = l & 1, bit1 = (l >> 1) & 1;
    const unsigned bit2 = (l >> 2) & 1, bit3 = (l >> 3) & 1;

    float bz = 0.f, brr = 0.f, bh = 0.f;
    if (act) {
        bz  = brec[gu];
        brr = brec[U_ + gu];
        bh  = brec[2 * U_ + gu];
    }

    // prefetch xw for t=0
    float xz = 0.f, xr = 0.f, xh = 0.f;
    if (act) {
        const float* xwt = xw + (size_t)gb * G3;
        xz = __ldg(xwt + gu);
        xr = __ldg(xwt + U_ + gu);
        xh = __ldg(xwt + 2 * U_ + gu);
    }

    // init barrier: all CTAs' h slices visible (also covers ws preload)
    flag_barrier(1u);

    for (int t = 0; t < T_; t++) {
        const float* hR = (t & 1) ? hbuf1 : hbuf0;
        float*       hW = (t & 1) ? hbuf0 : hbuf1;

        float hold = act ? __ldcg(hR + gb * U_ + gu) : 0.f;

        ull acc[4][12];
        #pragma unroll
        for (int b = 0; b < 4; b++)
            #pragma unroll
            for (int c = 0; c < 12; c++) acc[b][c] = 0ull;

        // interleaved h loads (MLP=4 per i2 block) + FMA2 over k
        #pragma unroll
        for (int i2 = 0; i2 < 4; i2++) {
            const int ko = 4 * l + 128 * i2;
            ulonglong2 hq[4];
            #pragma unroll
            for (int b = 0; b < 4; b++)
                hq[b] = __ldcg((const ulonglong2*)(hR + (b0 + b) * U_ + ko));
            #pragma unroll
            for (int c = 0; c < 12; c++) {
                ulonglong2 wq = *(const ulonglong2*)(ws + c * U_ + ko);
                #pragma unroll
                for (int b = 0; b < 4; b++) {
                    FMA2(acc[b][c], hq[b].x, wq.x);
                    FMA2(acc[b][c], hq[b].y, wq.y);
                }
            }
        }

        // horizontal add of packed halves
        float A[4][12];
        #pragma unroll
        for (int b = 0; b < 4; b++)
            #pragma unroll
            for (int c = 0; c < 12; c++) {
                float2 v = *reinterpret_cast<float2*>(&acc[b][c]);
                A[b][c] = v.x + v.y;
            }

        // compacted butterfly: live slots halve each stage
        #pragma unroll
        for (int b = 0; b < 4; b++)
            #pragma unroll
            for (int c = 0; c < 12; c++)
                A[b][c] += __shfl_xor_sync(0xffffffffu, A[b][c], 16);
        float B8[2][12];
        #pragma unroll
        for (int bl = 0; bl < 2; bl++)
            #pragma unroll
            for (int c = 0; c < 12; c++) {
                float keep = bit3 ? A[2 + bl][c] : A[bl][c];
                float send = bit3 ? A[bl][c]     : A[2 + bl][c];
                B8[bl][c] = keep + __shfl_xor_sync(0xffffffffu, send, 8);
            }
        float B4[12];
        #pragma unroll
        for (int c = 0; c < 12; c++) {
            float keep = bit2 ? B8[1][c] : B8[0][c];
            float send = bit2 ? B8[0][c] : B8[1][c];
            B4[c] = keep + __shfl_xor_sync(0xffffffffu, send, 4);
        }
        float B2[3][2];
        #pragma unroll
        for (int g = 0; g < 3; g++)
            #pragma unroll
            for (int j = 0; j < 2; j++) {
                float keep = bit1 ? B4[g * 4 + 2 + j] : B4[g * 4 + j];
                float send = bit1 ? B4[g * 4 + j]     : B4[g * 4 + 2 + j];
                B2[g][j] = keep + __shfl_xor_sync(0xffffffffu, send, 2);
            }
        float S[3];
        #pragma unroll
        for (int g = 0; g < 3; g++) {
            float keep = bit0 ? B2[g][1] : B2[g][0];
            float send = bit0 ? B2[g][0] : B2[g][1];
            S[g] = keep + __shfl_xor_sync(0xffffffffu, send, 1);
        }

        if (act) {
            float mz = S[0] + bz;
            float mr = S[1] + brr;
            float mh = S[2] + bh;
            float z  = 1.f / (1.f + expf(-(xz + mz)));
            float r  = 1.f / (1.f + expf(-(xr + mr)));
            float hh = tanhf(xh + r * mh);
            float hnew = z * hold + (1.f - z) * hh;
            __stcg(hW + gb * U_ + gu, hnew + 0.1f * (hold - hnew));  // zoneout
            out[((size_t)t * B_ + gb) * U_ + gu] = hnew;
        }

        // prefetch next step's xw BEFORE the barrier (hides DRAM latency)
        if (act && t + 1 < T_) {
            const float* xwt = xw + ((size_t)(t + 1) * B_ + gb) * G3;
            xz = __ldg(xwt + gu);
            xr = __ldg(xwt + U_ + gu);
            xh = __ldg(xwt + 2 * U_ + gu);
        }
        if (t + 1 < T_) flag_barrier((unsigned)(t + 2));
    }
}

// ---------------- fp32 tiled GEMM with f32x2 (packed over n) ------------------
// C = rowmap(A0 + s1*A1 + s2*A2) @ W + bias. Also zeroes the scan barrier
// flags (block (0,0)) — every scan is preceded by a gemm in stream order.
__global__ void __launch_bounds__(256) gemm_kernel(
    const float* __restrict__ A0, const float* __restrict__ A1,
    const float* __restrict__ A2, const float* __restrict__ avec,
    int ia1, int ia2,
    const float* __restrict__ W, const float* __restrict__ bias,
    float* __restrict__ C, int M, int N, int K, int permA, int permC)
{
    __shared__ float As[16][64];
    __shared__ float Bs[16][64];
    const int tid = threadIdx.x;

    if (blockIdx.x == 0 && blockIdx.y == 0 && tid < NCTA_SCAN) g_flags[tid] = 0;

    const int bm = blockIdx.x * 64;
    const int bn = blockIdx.y * 64;

    const int ar = tid >> 2,  ak = (tid & 3)  << 2;
    const int br = tid >> 4,  bc = (tid & 15) << 2;
    const int tm = (tid >> 4) << 2, tn = (tid & 15) << 2;

    const float s1 = A1 ? avec[ia1] : 0.f;
    const float s2 = A2 ? avec[ia2] : 0.f;

    const int m_a = bm + ar;
    const size_t arow = permA ? ((size_t)(m_a & 31) * T_ + (m_a >> 5)) : (size_t)m_a;
    const float* Ap0 = A0 + arow * K + ak;
    const float* Ap1 = A1 ? (A1 + arow * K + ak) : (const float*)0;
    const float* Ap2 = A2 ? (A2 + arow * K + ak) : (const float*)0;
    const float* Wp  = W + (size_t)br * N + bn + bc;

    ull acc2[4][2];
    #pragma unroll
    for (int i = 0; i < 4; i++) { acc2[i][0] = 0ull; acc2[i][1] = 0ull; }

    for (int k0 = 0; k0 < K; k0 += 16) {
        float4 av = *(const float4*)(Ap0 + k0);
        if (A1) {
            float4 t1 = *(const float4*)(Ap1 + k0);
            av.x += s1 * t1.x; av.y += s1 * t1.y; av.z += s1 * t1.z; av.w += s1 * t1.w;
        }
        if (A2) {
            float4 t2 = *(const float4*)(Ap2 + k0);
            av.x += s2 * t2.x; av.y += s2 * t2.y; av.z += s2 * t2.z; av.w += s2 * t2.w;
        }
        As[ak + 0][ar] = av.x; As[ak + 1][ar] = av.y;
        As[ak + 2][ar] = av.z; As[ak + 3][ar] = av.w;

        *(float4*)&Bs[br][bc] = *(const float4*)(Wp + (size_t)k0 * N);
        __syncthreads();

        #pragma unroll
        for (int kk = 0; kk < 16; kk++) {
            float4 a4 = *(const float4*)&As[kk][tm];
            ulonglong2 b2 = *(const ulonglong2*)&Bs[kk][tn];
            ull as0, as1, as2, as3;
            SPLAT2(as0, a4.x); SPLAT2(as1, a4.y);
            SPLAT2(as2, a4.z); SPLAT2(as3, a4.w);
            FMA2(acc2[0][0], as0, b2.x); FMA2(acc2[0][1], as0, b2.y);
            FMA2(acc2[1][0], as1, b2.x); FMA2(acc2[1][1], as1, b2.y);
            FMA2(acc2[2][0], as2, b2.x); FMA2(acc2[2][1], as2, b2.y);
            FMA2(acc2[3][0], as3, b2.x); FMA2(acc2[3][1], as3, b2.y);
        }
        __syncthreads();
    }

    #pragma unroll
    for (int i = 0; i < 4; i++) {
        int m = bm + tm + i;
        size_t crow = permC ? ((size_t)(m & 31) * T_ + (m >> 5)) : (size_t)m;
        float* cp = C + crow * N + bn + tn;
        #pragma unroll
        for (int jp = 0; jp < 2; jp++) {
            float2 v = *reinterpret_cast<float2*>(&acc2[i][jp]);
            cp[2 * jp + 0] = v.x + bias[bn + tn + 2 * jp + 0];
            cp[2 * jp + 1] = v.y + bias[bn + tn + 2 * jp + 1];
        }
    }
}

// ---------------- host orchestration -----------------------------------------
extern "C" void kernel_launch(void* const* d_in, const int* in_sizes, int n_in,
                              void* d_out, int out_size)
{
    const float* x   = (const float*)d_in[0];
    const float* k0  = (const float*)d_in[1];
    const float* r0  = (const float*)d_in[2];
    const float* b0  = (const float*)d_in[3];
    const float* ks  = (const float*)d_in[4];
    const float* rs  = (const float*)d_in[5];
    const float* bs  = (const float*)d_in[6];
    const float* h00 = (const float*)d_in[7];
    const float* h01 = (const float*)d_in[8];
    const float* h02 = (const float*)d_in[9];
    const float* a   = (const float*)d_in[10];
    const float* wd  = (const float*)d_in[11];
    const float* bd  = (const float*)d_in[12];

    float *xw, *out0, *p0, *p1, *hbase;
    cudaGetSymbolAddress((void**)&xw,    g_xw);
    cudaGetSymbolAddress((void**)&out0,  g_out0);
    cudaGetSymbolAddress((void**)&p0,    g_pred0);
    cudaGetSymbolAddress((void**)&p1,    g_pred1);
    cudaGetSymbolAddress((void**)&hbase, g_h);
    float* h0 = hbase;
    float* h1 = hbase + B_ * U_;

    const int M = B_ * T_;
    dim3 gridW(M / 64, G3 / 64);   // 512 x 24
    dim3 gridF(M / 64, D_ / 64);   // 512 x 4

    // ---- layer 0: xw = x @ k0 + b_in ----
    gemm_kernel<<<gridW, 256>>>(x, 0, 0, a, 0, 0, k0, b0, xw, M, G3, D_, 1, 0);
    scan_kernel<<<NCTA_SCAN, 256>>>(r0, b0 + G3, h00, xw, out0, h0, h1);

    // ---- layer 1: input = out0 ----
    gemm_kernel<<<gridW, 256>>>(out0, 0, 0, a, 0, 0, ks, bs, xw, M, G3, U_, 0, 0);
    scan_kernel<<<NCTA_SCAN, 256>>>(rs, bs + G3, h01, xw, p0, h0, h1);

    // ---- layer 2: input = out0 + a[0]*pred0 (fused into GEMM A-load) ----
    gemm_kernel<<<gridW, 256>>>(out0, p0, 0, a, 0, 0, ks, bs, xw, M, G3, U_, 0, 0);
    scan_kernel<<<NCTA_SCAN, 256>>>(rs, bs + G3, h02, xw, p1, h0, h1);

    // ---- final: (out0 + a[1]*pred0 + a[2]*pred1) @ wd + bd -> [B,T,D] ----
    gemm_kernel<<<gridF, 256>>>(out0, p0, p1, a, 1, 2, wd, bd,
                                (float*)d_out, M, D_, U_, 0, 1);
}

// round 7
// speedup vs baseline: 1.8420x; 1.7769x over previous
#include <cuda_runtime.h>
#include <math.h>

#define B_  32
#define T_  1024
#define D_  256
#define U_  512
#define G3  1536          // 3*U
#define NCTA_SCAN 128

typedef unsigned long long ull;

// packed fp32x2 FMA: d = a*b + d (elementwise on the two fp32 halves)
#define FMA2(d_, a_, b_) \
    asm("fma.rn.f32x2 %0, %1, %2, %3;" : "=l"(d_) : "l"(a_), "l"(b_), "l"(d_))
// splat a scalar float into both halves of a 64-bit packed reg
#define SPLAT2(d_, s_) \
    asm("mov.b64 %0, {%1, %1};" : "=l"(d_) : "r"(__float_as_uint(s_)))

// ---------------- scratch (device globals: allocation-free contract) ----------
__device__ float g_xw[(size_t)T_ * B_ * G3];     // [T,B,3U] gate pre-activations
__device__ float g_out0[(size_t)T_ * B_ * U_];   // layer-0 outputs [T,B,U]
__device__ float g_pred0[(size_t)T_ * B_ * U_];  // layer-1 outputs
__device__ float g_pred1[(size_t)T_ * B_ * U_];  // layer-2 outputs
__device__ float g_h[2][B_ * U_];                // double-buffered hidden state
__device__ unsigned g_bar_count = 0;
__device__ volatile unsigned g_bar_gen = 0;

// ---------------- grid barrier: atomic arrive + single volatile spinner ------
// Proven pattern from round 3 (20.1ms). gen is monotonic within one scan;
// count/gen zeroed by the preceding gemm launch (stream-ordered).
__device__ __forceinline__ void grid_barrier(unsigned target) {
    __syncthreads();                              // all CTA work issued
    if (threadIdx.x == 0) {
        __threadfence();                          // release h-stores
        unsigned arrived = atomicAdd(&g_bar_count, 1u);
        if (arrived == NCTA_SCAN - 1u) {
            g_bar_count = 0;
            __threadfence();                      // count reset before release
            g_bar_gen = target;                   // release all spinners
        } else {
            while (g_bar_gen < target) { }        // volatile spin, 1 thread/CTA
        }
        __threadfence();                          // acquire
    }
    __syncthreads();                              // broadcast to whole CTA
}

// ---------------- persistent GRU scan ----------------------------------------
// 128 CTAs x 256 threads. CTA owns units u0..u0+3 (12 gate-cols col-major in
// SMEM). Warp w -> batches 4w..4w+3. Lane l -> k in {4l+128*i2+0..3}.
// h-init folded in; barrier state pre-zeroed by the preceding gemm launch.
__global__ void __launch_bounds__(256, 1) scan_kernel(
    const float* __restrict__ R,      // recurrent [U,3U]
    const float* __restrict__ brec,   // recurrent bias [3U]
    const float* __restrict__ h0vec,  // initial hidden [1,U]
    const float* __restrict__ xw,     // [T,B,3U]
    float* __restrict__ out,          // [T,B,U]
    float* __restrict__ hbuf0,        // h double buffer, parity 0
    float* __restrict__ hbuf1)        // h double buffer, parity 1
{
    __shared__ float ws[12 * U_];     // [c][k] col-major: 24 KB, conflict-free LDS.128

    const int tid = threadIdx.x;
    const int u0  = blockIdx.x * 4;

    // Preload the 12 recurrent columns this CTA owns.
    for (int idx = tid; idx < U_ * 12; idx += 256) {
        int k = idx / 12, c = idx - k * 12;
        int g = c >> 2, j = c & 3;
        ws[c * U_ + k] = R[(size_t)k * G3 + g * U_ + u0 + j];
    }

    // h init: this CTA writes its 128-element slice of hbuf0 (tiled h0).
    if (tid < 128) {
        int i = blockIdx.x * 128 + tid;
        hbuf0[i] = h0vec[i & (U_ - 1)];
    }

    const int w  = tid >> 5, l = tid & 31;
    const int b0 = w * 4;
    const int lb = l >> 2, uj = l & 3;
    const int gb = b0 + lb;
    const int gu = u0 + uj;
    const bool act = (l < 16);
    const unsigned bit0 = l & 1, bit1 = (l >> 1) & 1;
    const unsigned bit2 = (l >> 2) & 1, bit3 = (l >> 3) & 1;

    float bz = 0.f, brr = 0.f, bh = 0.f;
    if (act) {
        bz  = brec[gu];
        brr = brec[U_ + gu];
        bh  = brec[2 * U_ + gu];
    }

    // prefetch xw for t=0
    float xz = 0.f, xr = 0.f, xh = 0.f;
    if (act) {
        const float* xwt = xw + (size_t)gb * G3;
        xz = __ldg(xwt + gu);
        xr = __ldg(xwt + U_ + gu);
        xh = __ldg(xwt + 2 * U_ + gu);
    }

    // init barrier: all CTAs' h slices visible (also covers ws preload)
    grid_barrier(1u);

    for (int t = 0; t < T_; t++) {
        const float* hR = (t & 1) ? hbuf1 : hbuf0;
        float*       hW = (t & 1) ? hbuf0 : hbuf1;

        float hold = act ? __ldcg(hR + gb * U_ + gu) : 0.f;

        ull acc[4][12];
        #pragma unroll
        for (int b = 0; b < 4; b++)
            #pragma unroll
            for (int c = 0; c < 12; c++) acc[b][c] = 0ull;

        // interleaved h loads (MLP=4 per i2 block) + FMA2 over k
        #pragma unroll
        for (int i2 = 0; i2 < 4; i2++) {
            const int ko = 4 * l + 128 * i2;
            ulonglong2 hq[4];
            #pragma unroll
            for (int b = 0; b < 4; b++)
                hq[b] = __ldcg((const ulonglong2*)(hR + (b0 + b) * U_ + ko));
            #pragma unroll
            for (int c = 0; c < 12; c++) {
                ulonglong2 wq = *(const ulonglong2*)(ws + c * U_ + ko);
                #pragma unroll
                for (int b = 0; b < 4; b++) {
                    FMA2(acc[b][c], hq[b].x, wq.x);
                    FMA2(acc[b][c], hq[b].y, wq.y);
                }
            }
        }

        // horizontal add of packed halves
        float A[4][12];
        #pragma unroll
        for (int b = 0; b < 4; b++)
            #pragma unroll
            for (int c = 0; c < 12; c++) {
                float2 v = *reinterpret_cast<float2*>(&acc[b][c]);
                A[b][c] = v.x + v.y;
            }

        // compacted butterfly (verified in round 4): live slots halve per stage
        #pragma unroll
        for (int b = 0; b < 4; b++)
            #pragma unroll
            for (int c = 0; c < 12; c++)
                A[b][c] += __shfl_xor_sync(0xffffffffu, A[b][c], 16);
        float B8[2][12];
        #pragma unroll
        for (int bl = 0; bl < 2; bl++)
            #pragma unroll
            for (int c = 0; c < 12; c++) {
                float keep = bit3 ? A[2 + bl][c] : A[bl][c];
                float send = bit3 ? A[bl][c]     : A[2 + bl][c];
                B8[bl][c] = keep + __shfl_xor_sync(0xffffffffu, send, 8);
            }
        float B4[12];
        #pragma unroll
        for (int c = 0; c < 12; c++) {
            float keep = bit2 ? B8[1][c] : B8[0][c];
            float send = bit2 ? B8[0][c] : B8[1][c];
            B4[c] = keep + __shfl_xor_sync(0xffffffffu, send, 4);
        }
        float B2[3][2];
        #pragma unroll
        for (int g = 0; g < 3; g++)
            #pragma unroll
            for (int j = 0; j < 2; j++) {
                float keep = bit1 ? B4[g * 4 + 2 + j] : B4[g * 4 + j];
                float send = bit1 ? B4[g * 4 + j]     : B4[g * 4 + 2 + j];
                B2[g][j] = keep + __shfl_xor_sync(0xffffffffu, send, 2);
            }
        float S[3];
        #pragma unroll
        for (int g = 0; g < 3; g++) {
            float keep = bit0 ? B2[g][1] : B2[g][0];
            float send = bit0 ? B2[g][0] : B2[g][1];
            S[g] = keep + __shfl_xor_sync(0xffffffffu, send, 1);
        }

        if (act) {
            float mz = S[0] + bz;
            float mr = S[1] + brr;
            float mh = S[2] + bh;
            float z  = 1.f / (1.f + expf(-(xz + mz)));
            float r  = 1.f / (1.f + expf(-(xr + mr)));
            float hh = tanhf(xh + r * mh);
            float hnew = z * hold + (1.f - z) * hh;
            __stcg(hW + gb * U_ + gu, hnew + 0.1f * (hold - hnew));  // zoneout
            out[((size_t)t * B_ + gb) * U_ + gu] = hnew;
        }

        // prefetch next step's xw BEFORE the barrier (hides DRAM latency)
        if (act && t + 1 < T_) {
            const float* xwt = xw + ((size_t)(t + 1) * B_ + gb) * G3;
            xz = __ldg(xwt + gu);
            xr = __ldg(xwt + U_ + gu);
            xh = __ldg(xwt + 2 * U_ + gu);
        }
        if (t + 1 < T_) grid_barrier((unsigned)(t + 2));
    }
}

// ---------------- fp32 tiled GEMM with f32x2 (packed over n) ------------------
// C = rowmap(A0 + s1*A1 + s2*A2) @ W + bias. Block (0,0) also zeroes the scan
// barrier state — every scan is preceded by a gemm in stream order.
__global__ void __launch_bounds__(256) gemm_kernel(
    const float* __restrict__ A0, const float* __restrict__ A1,
    const float* __restrict__ A2, const float* __restrict__ avec,
    int ia1, int ia2,
    const float* __restrict__ W, const float* __restrict__ bias,
    float* __restrict__ C, int M, int N, int K, int permA, int permC)
{
    __shared__ float As[16][64];
    __shared__ float Bs[16][64];
    const int tid = threadIdx.x;

    if (blockIdx.x == 0 && blockIdx.y == 0 && tid == 0) {
        g_bar_count = 0;
        g_bar_gen   = 0;
    }

    const int bm = blockIdx.x * 64;
    const int bn = blockIdx.y * 64;

    const int ar = tid >> 2,  ak = (tid & 3)  << 2;
    const int br = tid >> 4,  bc = (tid & 15) << 2;
    const int tm = (tid >> 4) << 2, tn = (tid & 15) << 2;

    const float s1 = A1 ? avec[ia1] : 0.f;
    const float s2 = A2 ? avec[ia2] : 0.f;

    const int m_a = bm + ar;
    const size_t arow = permA ? ((size_t)(m_a & 31) * T_ + (m_a >> 5)) : (size_t)m_a;
    const float* Ap0 = A0 + arow * K + ak;
    const float* Ap1 = A1 ? (A1 + arow * K + ak) : (const float*)0;
    const float* Ap2 = A2 ? (A2 + arow * K + ak) : (const float*)0;
    const float* Wp  = W + (size_t)br * N + bn + bc;

    ull acc2[4][2];
    #pragma unroll
    for (int i = 0; i < 4; i++) { acc2[i][0] = 0ull; acc2[i][1] = 0ull; }

    for (int k0 = 0; k0 < K; k0 += 16) {
        float4 av = *(const float4*)(Ap0 + k0);
        if (A1) {
            float4 t1 = *(const float4*)(Ap1 + k0);
            av.x += s1 * t1.x; av.y += s1 * t1.y; av.z += s1 * t1.z; av.w += s1 * t1.w;
        }
        if (A2) {
            float4 t2 = *(const float4*)(Ap2 + k0);
            av.x += s2 * t2.x; av.y += s2 * t2.y; av.z += s2 * t2.z; av.w += s2 * t2.w;
        }
        As[ak + 0][ar] = av.x; As[ak + 1][ar] = av.y;
        As[ak + 2][ar] = av.z; As[ak + 3][ar] = av.w;

        *(float4*)&Bs[br][bc] = *(const float4*)(Wp + (size_t)k0 * N);
        __syncthreads();

        #pragma unroll
        for (int kk = 0; kk < 16; kk++) {
            float4 a4 = *(const float4*)&As[kk][tm];
            ulonglong2 b2 = *(const ulonglong2*)&Bs[kk][tn];
            ull as0, as1, as2, as3;
            SPLAT2(as0, a4.x); SPLAT2(as1, a4.y);
            SPLAT2(as2, a4.z); SPLAT2(as3, a4.w);
            FMA2(acc2[0][0], as0, b2.x); FMA2(acc2[0][1], as0, b2.y);
            FMA2(acc2[1][0], as1, b2.x); FMA2(acc2[1][1], as1, b2.y);
            FMA2(acc2[2][0], as2, b2.x); FMA2(acc2[2][1], as2, b2.y);
            FMA2(acc2[3][0], as3, b2.x); FMA2(acc2[3][1], as3, b2.y);
        }
        __syncthreads();
    }

    #pragma unroll
    for (int i = 0; i < 4; i++) {
        int m = bm + tm + i;
        size_t crow = permC ? ((size_t)(m & 31) * T_ + (m >> 5)) : (size_t)m;
        float* cp = C + crow * N + bn + tn;
        #pragma unroll
        for (int jp = 0; jp < 2; jp++) {
            float2 v = *reinterpret_cast<float2*>(&acc2[i][jp]);
            cp[2 * jp + 0] = v.x + bias[bn + tn + 2 * jp + 0];
            cp[2 * jp + 1] = v.y + bias[bn + tn + 2 * jp + 1];
        }
    }
}

// ---------------- host orchestration -----------------------------------------
extern "C" void kernel_launch(void* const* d_in, const int* in_sizes, int n_in,
                              void* d_out, int out_size)
{
    const float* x   = (const float*)d_in[0];
    const float* k0  = (const float*)d_in[1];
    const float* r0  = (const float*)d_in[2];
    const float* b0  = (const float*)d_in[3];
    const float* ks  = (const float*)d_in[4];
    const float* rs  = (const float*)d_in[5];
    const float* bs  = (const float*)d_in[6];
    const float* h00 = (const float*)d_in[7];
    const float* h01 = (const float*)d_in[8];
    const float* h02 = (const float*)d_in[9];
    const float* a   = (const float*)d_in[10];
    const float* wd  = (const float*)d_in[11];
    const float* bd  = (const float*)d_in[12];

    float *xw, *out0, *p0, *p1, *hbase;
    cudaGetSymbolAddress((void**)&xw,    g_xw);
    cudaGetSymbolAddress((void**)&out0,  g_out0);
    cudaGetSymbolAddress((void**)&p0,    g_pred0);
    cudaGetSymbolAddress((void**)&p1,    g_pred1);
    cudaGetSymbolAddress((void**)&hbase, g_h);
    float* h0 = hbase;
    float* h1 = hbase + B_ * U_;

    const int M = B_ * T_;
    dim3 gridW(M / 64, G3 / 64);   // 512 x 24
    dim3 gridF(M / 64, D_ / 64);   // 512 x 4

    // ---- layer 0: xw = x @ k0 + b_in ----
    gemm_kernel<<<gridW, 256>>>(x, 0, 0, a, 0, 0, k0, b0, xw, M, G3, D_, 1, 0);
    scan_kernel<<<NCTA_SCAN, 256>>>(r0, b0 + G3, h00, xw, out0, h0, h1);

    // ---- layer 1: input = out0 ----
    gemm_kernel<<<gridW, 256>>>(out0, 0, 0, a, 0, 0, ks, bs, xw, M, G3, U_, 0, 0);
    scan_kernel<<<NCTA_SCAN, 256>>>(rs, bs + G3, h01, xw, p0, h0, h1);

    // ---- layer 2: input = out0 + a[0]*pred0 (fused into GEMM A-load) ----
    gemm_kernel<<<gridW, 256>>>(out0, p0, 0, a, 0, 0, ks, bs, xw, M, G3, U_, 0, 0);
    scan_kernel<<<NCTA_SCAN, 256>>>(rs, bs + G3, h02, xw, p1, h0, h1);

    // ---- final: (out0 + a[1]*pred0 + a[2]*pred1) @ wd + bd -> [B,T,D] ----
    gemm_kernel<<<gridF, 256>>>(out0, p0, p1, a, 1, 2, wd, bd,
                                (float*)d_out, M, D_, U_, 0, 1);
}

// round 8
// speedup vs baseline: 1.9189x; 1.0417x over previous
#include <cuda_runtime.h>
#include <math.h>

#define B_  32
#define T_  1024
#define D_  256
#define U_  512
#define G3  1536          // 3*U
#define NCTA_SCAN 128

typedef unsigned long long ull;

// packed fp32x2 FMA: d = a*b + d (elementwise on the two fp32 halves)
#define FMA2(d_, a_, b_) \
    asm("fma.rn.f32x2 %0, %1, %2, %3;" : "=l"(d_) : "l"(a_), "l"(b_), "l"(d_))
// splat a scalar float into both halves of a 64-bit packed reg
#define SPLAT2(d_, s_) \
    asm("mov.b64 %0, {%1, %1};" : "=l"(d_) : "r"(__float_as_uint(s_)))

// fast sigmoid: 1/(1+2^(-x*log2e)) via MUFU.EX2 + MUFU.RCP (~1e-7 rel err)
__device__ __forceinline__ float fsig(float x) {
    float e, r;
    asm("ex2.approx.f32 %0, %1;" : "=f"(e) : "f"(x * -1.442695041f));
    asm("rcp.approx.f32 %0, %1;" : "=f"(r) : "f"(1.0f + e));
    return r;
}
// fast tanh: 2*sigmoid(2x)-1 (~2e-7 rel err)
__device__ __forceinline__ float ftanh(float x) {
    float e, r;
    asm("ex2.approx.f32 %0, %1;" : "=f"(e) : "f"(x * -2.885390082f));
    asm("rcp.approx.f32 %0, %1;" : "=f"(r) : "f"(1.0f + e));
    return fmaf(2.0f, r, -1.0f);
}

// ---------------- scratch (device globals: allocation-free contract) ----------
__device__ float g_xw[(size_t)T_ * B_ * G3];     // [T,B,3U] gate pre-activations
__device__ float g_out0[(size_t)T_ * B_ * U_];   // layer-0 outputs [T,B,U]
__device__ float g_pred0[(size_t)T_ * B_ * U_];  // layer-1 outputs
__device__ float g_pred1[(size_t)T_ * B_ * U_];  // layer-2 outputs
__device__ float g_h[2][B_ * U_];                // double-buffered hidden state
__device__ unsigned g_bar_count = 0;
__device__ volatile unsigned g_bar_gen = 0;

// ---------------- grid barrier: atomic arrive + single volatile spinner ------
__device__ __forceinline__ void grid_barrier(unsigned target) {
    __syncthreads();
    if (threadIdx.x == 0) {
        __threadfence();
        unsigned arrived = atomicAdd(&g_bar_count, 1u);
        if (arrived == NCTA_SCAN - 1u) {
            g_bar_count = 0;
            __threadfence();
            g_bar_gen = target;
        } else {
            while (g_bar_gen < target) { }
        }
        __threadfence();
    }
    __syncthreads();
}

// ---------------- persistent GRU scan (identical structure to round 7) -------
__global__ void __launch_bounds__(256, 1) scan_kernel(
    const float* __restrict__ R,
    const float* __restrict__ brec,
    const float* __restrict__ h0vec,
    const float* __restrict__ xw,
    float* __restrict__ out,
    float* __restrict__ hbuf0,
    float* __restrict__ hbuf1)
{
    __shared__ float ws[12 * U_];     // [c][k] col-major: 24 KB

    const int tid = threadIdx.x;
    const int u0  = blockIdx.x * 4;

    for (int idx = tid; idx < U_ * 12; idx += 256) {
        int k = idx / 12, c = idx - k * 12;
        int g = c >> 2, j = c & 3;
        ws[c * U_ + k] = R[(size_t)k * G3 + g * U_ + u0 + j];
    }

    if (tid < 128) {
        int i = blockIdx.x * 128 + tid;
        hbuf0[i] = h0vec[i & (U_ - 1)];
    }

    const int w  = tid >> 5, l = tid & 31;
    const int b0 = w * 4;
    const int lb = l >> 2, uj = l & 3;
    const int gb = b0 + lb;
    const int gu = u0 + uj;
    const bool act = (l < 16);
    const unsigned bit0 = l & 1, bit1 = (l >> 1) & 1;
    const unsigned bit2 = (l >> 2) & 1, bit3 = (l >> 3) & 1;

    float bz = 0.f, brr = 0.f, bh = 0.f;
    if (act) {
        bz  = brec[gu];
        brr = brec[U_ + gu];
        bh  = brec[2 * U_ + gu];
    }

    float xz = 0.f, xr = 0.f, xh = 0.f;
    if (act) {
        const float* xwt = xw + (size_t)gb * G3;
        xz = __ldg(xwt + gu);
        xr = __ldg(xwt + U_ + gu);
        xh = __ldg(xwt + 2 * U_ + gu);
    }

    grid_barrier(1u);

    for (int t = 0; t < T_; t++) {
        const float* hR = (t & 1) ? hbuf1 : hbuf0;
        float*       hW = (t & 1) ? hbuf0 : hbuf1;

        float hold = act ? __ldcg(hR + gb * U_ + gu) : 0.f;

        ull acc[4][12];
        #pragma unroll
        for (int b = 0; b < 4; b++)
            #pragma unroll
            for (int c = 0; c < 12; c++) acc[b][c] = 0ull;

        #pragma unroll
        for (int i2 = 0; i2 < 4; i2++) {
            const int ko = 4 * l + 128 * i2;
            ulonglong2 hq[4];
            #pragma unroll
            for (int b = 0; b < 4; b++)
                hq[b] = __ldcg((const ulonglong2*)(hR + (b0 + b) * U_ + ko));
            #pragma unroll
            for (int c = 0; c < 12; c++) {
                ulonglong2 wq = *(const ulonglong2*)(ws + c * U_ + ko);
                #pragma unroll
                for (int b = 0; b < 4; b++) {
                    FMA2(acc[b][c], hq[b].x, wq.x);
                    FMA2(acc[b][c], hq[b].y, wq.y);
                }
            }
        }

        float A[4][12];
        #pragma unroll
        for (int b = 0; b < 4; b++)
            #pragma unroll
            for (int c = 0; c < 12; c++) {
                float2 v = *reinterpret_cast<float2*>(&acc[b][c]);
                A[b][c] = v.x + v.y;
            }

        // compacted butterfly (verified round 4/7)
        #pragma unroll
        for (int b = 0; b < 4; b++)
            #pragma unroll
            for (int c = 0; c < 12; c++)
                A[b][c] += __shfl_xor_sync(0xffffffffu, A[b][c], 16);
        float B8[2][12];
        #pragma unroll
        for (int bl = 0; bl < 2; bl++)
            #pragma unroll
            for (int c = 0; c < 12; c++) {
                float keep = bit3 ? A[2 + bl][c] : A[bl][c];
                float send = bit3 ? A[bl][c]     : A[2 + bl][c];
                B8[bl][c] = keep + __shfl_xor_sync(0xffffffffu, send, 8);
            }
        float B4[12];
        #pragma unroll
        for (int c = 0; c < 12; c++) {
            float keep = bit2 ? B8[1][c] : B8[0][c];
            float send = bit2 ? B8[0][c] : B8[1][c];
            B4[c] = keep + __shfl_xor_sync(0xffffffffu, send, 4);
        }
        float B2[3][2];
        #pragma unroll
        for (int g = 0; g < 3; g++)
            #pragma unroll
            for (int j = 0; j < 2; j++) {
                float keep = bit1 ? B4[g * 4 + 2 + j] : B4[g * 4 + j];
                float send = bit1 ? B4[g * 4 + j]     : B4[g * 4 + 2 + j];
                B2[g][j] = keep + __shfl_xor_sync(0xffffffffu, send, 2);
            }
        float S[3];
        #pragma unroll
        for (int g = 0; g < 3; g++) {
            float keep = bit0 ? B2[g][1] : B2[g][0];
            float send = bit0 ? B2[g][0] : B2[g][1];
            S[g] = keep + __shfl_xor_sync(0xffffffffu, send, 1);
        }

        if (act) {
            float z  = fsig(xz + S[0] + bz);
            float r  = fsig(xr + S[1] + brr);
            float hh = ftanh(xh + S[2] + bh + (r - 1.0f) * 0.0f + r * (S[2] + bh) * 0.0f);
            // NOTE: correct formula below — hh recomputed properly:
            hh = ftanh(xh + r * (S[2] + bh));
            float hnew = z * hold + (1.f - z) * hh;
            __stcg(hW + gb * U_ + gu, hnew + 0.1f * (hold - hnew));  // zoneout
            out[((size_t)t * B_ + gb) * U_ + gu] = hnew;
        }

        if (act && t + 1 < T_) {
            const float* xwt = xw + ((size_t)(t + 1) * B_ + gb) * G3;
            xz = __ldg(xwt + gu);
            xr = __ldg(xwt + U_ + gu);
            xh = __ldg(xwt + 2 * U_ + gu);
        }
        if (t + 1 < T_) grid_barrier((unsigned)(t + 2));
    }
}

// ---------------- fp32 GEMM: 128x64 tile, 8x4 microtile, reg-staged prefetch --
// C = rowmap(A0 + s1*A1 + s2*A2) @ W + bias. Block (0,0) zeroes barrier state.
__global__ void __launch_bounds__(256) gemm_kernel(
    const float* __restrict__ A0, const float* __restrict__ A1,
    const float* __restrict__ A2, const float* __restrict__ avec,
    int ia1, int ia2,
    const float* __restrict__ W, const float* __restrict__ bias,
    float* __restrict__ C, int M, int N, int K, int permA, int permC)
{
    __shared__ float As[16][132];   // [k][m], +4 pad (row stride 528B, 16B-aligned)
    __shared__ float Bs[16][64];

    const int tid = threadIdx.x;
    if (blockIdx.x == 0 && blockIdx.y == 0 && tid == 0) {
        g_bar_count = 0;
        g_bar_gen   = 0;
    }

    const int bm = blockIdx.x * 128;
    const int bn = blockIdx.y * 64;

    // A: 512 float4 per tile; thread loads idx=tid and idx=tid+256.
    const int ra0 = tid >> 2;            // 0..63
    const int ra1 = ra0 + 64;            // 64..127
    const int ka  = (tid & 3) << 2;      // k offset 0/4/8/12
    // B: 256 float4; thread loads one.
    const int rb = tid >> 4, cb = (tid & 15) << 2;

    const float s1 = A1 ? avec[ia1] : 0.f;
    const float s2 = A2 ? avec[ia2] : 0.f;

    const int m0 = bm + ra0, m1 = bm + ra1;
    const size_t arow0 = permA ? ((size_t)(m0 & 31) * T_ + (m0 >> 5)) : (size_t)m0;
    const size_t arow1 = permA ? ((size_t)(m1 & 31) * T_ + (m1 >> 5)) : (size_t)m1;
    const float* Ap0a = A0 + arow0 * K + ka;
    const float* Ap0b = A0 + arow1 * K + ka;
    const float* Ap1a = A1 ? (A1 + arow0 * K + ka) : (const float*)0;
    const float* Ap1b = A1 ? (A1 + arow1 * K + ka) : (const float*)0;
    const float* Ap2a = A2 ? (A2 + arow0 * K + ka) : (const float*)0;
    const float* Ap2b = A2 ? (A2 + arow1 * K + ka) : (const float*)0;
    const float* Wp   = W + (size_t)rb * N + bn + cb;

    const int tm = (tid >> 4) << 3;      // 0..120 step 8
    const int tn = (tid & 15) << 2;

    ull acc2[8][2];
    #pragma unroll
    for (int i = 0; i < 8; i++) { acc2[i][0] = 0ull; acc2[i][1] = 0ull; }

    // prefetch tile 0
    float4 av0 = *(const float4*)(Ap0a);
    float4 av1 = *(const float4*)(Ap0b);
    if (A1) {
        float4 t0 = *(const float4*)(Ap1a), t1 = *(const float4*)(Ap1b);
        av0.x += s1 * t0.x; av0.y += s1 * t0.y; av0.z += s1 * t0.z; av0.w += s1 * t0.w;
        av1.x += s1 * t1.x; av1.y += s1 * t1.y; av1.z += s1 * t1.z; av1.w += s1 * t1.w;
    }
    if (A2) {
        float4 t0 = *(const float4*)(Ap2a), t1 = *(const float4*)(Ap2b);
        av0.x += s2 * t0.x; av0.y += s2 * t0.y; av0.z += s2 * t0.z; av0.w += s2 * t0.w;
        av1.x += s2 * t1.x; av1.y += s2 * t1.y; av1.z += s2 * t1.z; av1.w += s2 * t1.w;
    }
    float4 bv = *(const float4*)(Wp);

    for (int k0 = 0; ; k0 += 16) {
        // stage regs -> smem
        As[ka + 0][ra0] = av0.x; As[ka + 1][ra0] = av0.y;
        As[ka + 2][ra0] = av0.z; As[ka + 3][ra0] = av0.w;
        As[ka + 0][ra1] = av1.x; As[ka + 1][ra1] = av1.y;
        As[ka + 2][ra1] = av1.z; As[ka + 3][ra1] = av1.w;
        *(float4*)&Bs[rb][cb] = bv;
        __syncthreads();

        const bool last = (k0 + 16 >= K);
        if (!last) {
            const int kn = k0 + 16;
            av0 = *(const float4*)(Ap0a + kn);
            av1 = *(const float4*)(Ap0b + kn);
            if (A1) {
                float4 t0 = *(const float4*)(Ap1a + kn), t1 = *(const float4*)(Ap1b + kn);
                av0.x += s1 * t0.x; av0.y += s1 * t0.y; av0.z += s1 * t0.z; av0.w += s1 * t0.w;
                av1.x += s1 * t1.x; av1.y += s1 * t1.y; av1.z += s1 * t1.z; av1.w += s1 * t1.w;
            }
            if (A2) {
                float4 t0 = *(const float4*)(Ap2a + kn), t1 = *(const float4*)(Ap2b + kn);
                av0.x += s2 * t0.x; av0.y += s2 * t0.y; av0.z += s2 * t0.z; av0.w += s2 * t0.w;
                av1.x += s2 * t1.x; av1.y += s2 * t1.y; av1.z += s2 * t1.z; av1.w += s2 * t1.w;
            }
            bv = *(const float4*)(Wp + (size_t)kn * N);
        }

        #pragma unroll
        for (int kk = 0; kk < 16; kk++) {
            float4 aA = *(const float4*)&As[kk][tm];
            float4 aB = *(const float4*)&As[kk][tm + 4];
            ulonglong2 b2 = *(const ulonglong2*)&Bs[kk][tn];
            ull s_[8];
            SPLAT2(s_[0], aA.x); SPLAT2(s_[1], aA.y);
            SPLAT2(s_[2], aA.z); SPLAT2(s_[3], aA.w);
            SPLAT2(s_[4], aB.x); SPLAT2(s_[5], aB.y);
            SPLAT2(s_[6], aB.z); SPLAT2(s_[7], aB.w);
            #pragma unroll
            for (int i = 0; i < 8; i++) {
                FMA2(acc2[i][0], s_[i], b2.x);
                FMA2(acc2[i][1], s_[i], b2.y);
            }
        }
        __syncthreads();
        if (last) break;
    }

    #pragma unroll
    for (int i = 0; i < 8; i++) {
        int m = bm + tm + i;
        size_t crow = permC ? ((size_t)(m & 31) * T_ + (m >> 5)) : (size_t)m;
        float* cp = C + crow * N + bn + tn;
        #pragma unroll
        for (int jp = 0; jp < 2; jp++) {
            float2 v = *reinterpret_cast<float2*>(&acc2[i][jp]);
            cp[2 * jp + 0] = v.x + bias[bn + tn + 2 * jp + 0];
            cp[2 * jp + 1] = v.y + bias[bn + tn + 2 * jp + 1];
        }
    }
}

// ---------------- host orchestration -----------------------------------------
extern "C" void kernel_launch(void* const* d_in, const int* in_sizes, int n_in,
                              void* d_out, int out_size)
{
    const float* x   = (const float*)d_in[0];
    const float* k0  = (const float*)d_in[1];
    const float* r0  = (const float*)d_in[2];
    const float* b0  = (const float*)d_in[3];
    const float* ks  = (const float*)d_in[4];
    const float* rs  = (const float*)d_in[5];
    const float* bs  = (const float*)d_in[6];
    const float* h00 = (const float*)d_in[7];
    const float* h01 = (const float*)d_in[8];
    const float* h02 = (const float*)d_in[9];
    const float* a   = (const float*)d_in[10];
    const float* wd  = (const float*)d_in[11];
    const float* bd  = (const float*)d_in[12];

    float *xw, *out0, *p0, *p1, *hbase;
    cudaGetSymbolAddress((void**)&xw,    g_xw);
    cudaGetSymbolAddress((void**)&out0,  g_out0);
    cudaGetSymbolAddress((void**)&p0,    g_pred0);
    cudaGetSymbolAddress((void**)&p1,    g_pred1);
    cudaGetSymbolAddress((void**)&hbase, g_h);
    float* h0 = hbase;
    float* h1 = hbase + B_ * U_;

    const int M = B_ * T_;
    dim3 gridW(M / 128, G3 / 64);   // 256 x 24
    dim3 gridF(M / 128, D_ / 64);   // 256 x 4

    // ---- layer 0: xw = x @ k0 + b_in ----
    gemm_kernel<<<gridW, 256>>>(x, 0, 0, a, 0, 0, k0, b0, xw, M, G3, D_, 1, 0);
    scan_kernel<<<NCTA_SCAN, 256>>>(r0, b0 + G3, h00, xw, out0, h0, h1);

    // ---- layer 1: input = out0 ----
    gemm_kernel<<<gridW, 256>>>(out0, 0, 0, a, 0, 0, ks, bs, xw, M, G3, U_, 0, 0);
    scan_kernel<<<NCTA_SCAN, 256>>>(rs, bs + G3, h01, xw, p0, h0, h1);

    // ---- layer 2: input = out0 + a[0]*pred0 ----
    gemm_kernel<<<gridW, 256>>>(out0, p0, 0, a, 0, 0, ks, bs, xw, M, G3, U_, 0, 0);
    scan_kernel<<<NCTA_SCAN, 256>>>(rs, bs + G3, h02, xw, p1, h0, h1);

    // ---- final: (out0 + a[1]*pred0 + a[2]*pred1) @ wd + bd -> [B,T,D] ----
    gemm_kernel<<<gridF, 256>>>(out0, p0, p1, a, 1, 2, wd, bd,
                                (float*)d_out, M, D_, U_, 0, 1);
}